// round 2
// baseline (speedup 1.0000x reference)
#include <cuda_runtime.h>
#include <math.h>

#define NN 768
#define HH 12
#define SQKd 16
#define SVd 16
#define PQKd 4
#define PVd 8
#define C1d 384
#define C2d 128
#define CONCAT 2112   // H*(SV + 4*PV + C2) = 12*176

// -------- scratch (device globals; no allocation allowed) --------
__device__ float g_q  [NN*HH*SQKd];        // [n][h*16+c], scaled by 0.25
__device__ float g_k  [NN*HH*SQKd];        // [n][h*16+c]
__device__ float g_vh [HH*NN*SVd];         // [h][n][c]
__device__ float g_qp [NN*HH*PQKd*3];      // [n][h*12 + p*3 + d] global frame
__device__ float g_kp [NN*HH*PQKd*3];
__device__ float g_vph[HH*NN*PVd*3];       // [h][n][p*3+d] global frame
__device__ float g_sq [NN*HH];
__device__ float g_sk [NN*HH];
__device__ float g_attn[(size_t)NN*HH*NN]; // [q][h][k]  (logits -> attn in place)
__device__ float g_rpg[NN*HH*PVd*3];       // attn-weighted vp (global frame)
__device__ float g_cbuf[NN*CONCAT];        // concat features per residue

// =====================================================================
// K1: projections + frame application. 768 blocks x 576 threads.
// Each thread does two 384-length dots (one qkv output, one point output).
// =====================================================================
__global__ void k1_proj(const float* __restrict__ act,
                        const float* __restrict__ rot,
                        const float* __restrict__ trans,
                        const float* __restrict__ wq, const float* __restrict__ wk,
                        const float* __restrict__ wv,
                        const float* __restrict__ wqp, const float* __restrict__ bqp,
                        const float* __restrict__ wkp, const float* __restrict__ bkp,
                        const float* __restrict__ wvp, const float* __restrict__ bvp) {
    int n = blockIdx.x;
    int tid = threadIdx.x; // 576
    __shared__ float s_act[C1d];
    __shared__ float s_raw[576];       // qp raw 144 | kp raw 144 | vp raw 288
    __shared__ float s_app[96*3];      // applied qp(48) + kp(48) points
    __shared__ float s_rot[9], s_tr[3];

    for (int i = tid; i < C1d; i += 576) s_act[i] = act[n*C1d + i];
    if (tid < 9) s_rot[tid] = rot[n*9 + tid];
    if (tid < 3) s_tr[tid]  = trans[n*3 + tid];
    __syncthreads();

    // ---- q / k / v ----
    {
        const float* w; int o; int which;
        if (tid < 192)      { w = wq;  o = tid;       which = 0; }
        else if (tid < 384) { w = wk;  o = tid - 192; which = 1; }
        else                { w = wv;  o = tid - 384; which = 2; }
        float acc = 0.f;
        #pragma unroll 8
        for (int c = 0; c < C1d; c++) acc += s_act[c] * w[c*192 + o];
        if (which == 0)      g_q[n*192 + o] = acc * 0.25f;       // sqrt(1/16)
        else if (which == 1) g_k[n*192 + o] = acc;
        else                 g_vh[(o >> 4)*(NN*SVd) + n*SVd + (o & 15)] = acc;
    }

    // ---- point raws ----
    {
        const float* w; const float* b; int o; int stride;
        if (tid < 144)      { w = wqp; b = bqp; o = tid;       stride = 144; }
        else if (tid < 288) { w = wkp; b = bkp; o = tid - 144; stride = 144; }
        else                { w = wvp; b = bvp; o = tid - 288; stride = 288; }
        float acc = b[o];
        #pragma unroll 8
        for (int c = 0; c < C1d; c++) acc += s_act[c] * w[c*stride + o];
        s_raw[tid] = acc;
    }
    __syncthreads();

    // ---- apply rigid frames ----
    if (tid < 192) {
        float l0, l1, l2;
        if (tid < 48) {                      // qp: raw[h*12 + d*4 + p]
            int h = tid >> 2, p = tid & 3;
            l0 = s_raw[h*12 + 0*4 + p]; l1 = s_raw[h*12 + 1*4 + p]; l2 = s_raw[h*12 + 2*4 + p];
        } else if (tid < 96) {
            int j = tid - 48; int h = j >> 2, p = j & 3;
            l0 = s_raw[144 + h*12 + 0*4 + p]; l1 = s_raw[144 + h*12 + 1*4 + p]; l2 = s_raw[144 + h*12 + 2*4 + p];
        } else {                             // vp: raw[h*24 + d*8 + p]
            int j = tid - 96; int h = j >> 3, p = j & 7;
            l0 = s_raw[288 + h*24 + 0*8 + p]; l1 = s_raw[288 + h*24 + 1*8 + p]; l2 = s_raw[288 + h*24 + 2*8 + p];
        }
        float gx = s_rot[0]*l0 + s_rot[1]*l1 + s_rot[2]*l2 + s_tr[0];
        float gy = s_rot[3]*l0 + s_rot[4]*l1 + s_rot[5]*l2 + s_tr[1];
        float gz = s_rot[6]*l0 + s_rot[7]*l1 + s_rot[8]*l2 + s_tr[2];
        if (tid < 48) {
            g_qp[n*144 + tid*3+0] = gx; g_qp[n*144 + tid*3+1] = gy; g_qp[n*144 + tid*3+2] = gz;
            s_app[tid*3+0] = gx; s_app[tid*3+1] = gy; s_app[tid*3+2] = gz;
        } else if (tid < 96) {
            int j = tid - 48;
            g_kp[n*144 + j*3+0] = gx; g_kp[n*144 + j*3+1] = gy; g_kp[n*144 + j*3+2] = gz;
            s_app[tid*3+0] = gx; s_app[tid*3+1] = gy; s_app[tid*3+2] = gz;
        } else {
            int j = tid - 96; int h = j >> 3, p = j & 7;
            g_vph[h*(NN*PVd*3) + n*(PVd*3) + p*3+0] = gx;
            g_vph[h*(NN*PVd*3) + n*(PVd*3) + p*3+1] = gy;
            g_vph[h*(NN*PVd*3) + n*(PVd*3) + p*3+2] = gz;
        }
    }
    __syncthreads();

    // ---- sq / sk : sum over 4 points of |pt|^2 per head ----
    if (tid < 24) {
        int h = tid % 12;
        int base = (tid < 12) ? 0 : 144;   // qp then kp in s_app
        float s = 0.f;
        #pragma unroll
        for (int p = 0; p < 4; p++) {
            float x = s_app[base + (h*4+p)*3+0];
            float y = s_app[base + (h*4+p)*3+1];
            float z = s_app[base + (h*4+p)*3+2];
            s += x*x + y*y + z*z;
        }
        if (tid < 12) g_sq[n*12 + h] = s; else g_sk[n*12 + h] = s;
    }
}

// =====================================================================
// K2: fused logits. Grid (96 qtiles of 8, 48 ktiles of 16), 128 threads.
// Thread owns one (q,k) pair, accumulates all 12 heads.
// =====================================================================
__global__ void k2_logits(const float* __restrict__ act2d,
                          const float* __restrict__ w2d,
                          const float* __restrict__ b2d,
                          const float* __restrict__ tw,
                          const float* __restrict__ smask) {
    __shared__ float s_q[8][192], s_k[16][192];
    __shared__ float s_qp[8][144], s_kp[16][144];
    __shared__ float s_w2d[128*12];
    __shared__ float s_sq[8][12], s_sk[16][12];
    __shared__ float s_pw[12], s_b2d[12], s_mq[8], s_mk[16];
    int tid = threadIdx.x;
    int q0 = blockIdx.x * 8, k0 = blockIdx.y * 16;

    for (int i = tid; i < 8*192;  i += 128) s_q[i/192][i%192]  = g_q[(q0 + i/192)*192 + i%192];
    for (int i = tid; i < 16*192; i += 128) s_k[i/192][i%192]  = g_k[(k0 + i/192)*192 + i%192];
    for (int i = tid; i < 8*144;  i += 128) s_qp[i/144][i%144] = g_qp[(q0 + i/144)*144 + i%144];
    for (int i = tid; i < 16*144; i += 128) s_kp[i/144][i%144] = g_kp[(k0 + i/144)*144 + i%144];
    for (int i = tid; i < 1536;   i += 128) s_w2d[i] = w2d[i];
    for (int i = tid; i < 96;     i += 128) s_sq[i/12][i%12] = g_sq[(q0 + i/12)*12 + i%12];
    for (int i = tid; i < 192;    i += 128) s_sk[i/12][i%12] = g_sk[(k0 + i/12)*12 + i%12];
    if (tid < 12) { s_pw[tid] = 0.23570226039f * log1pf(expf(tw[tid])); s_b2d[tid] = b2d[tid]; }
    if (tid < 8)  s_mq[tid] = smask[q0 + tid];
    if (tid < 16) s_mk[tid] = smask[k0 + tid];
    __syncthreads();

    int qi = tid >> 4, ki = tid & 15;
    int q = q0 + qi, k = k0 + ki;

    float acc[12];
    #pragma unroll
    for (int h = 0; h < 12; h++) acc[h] = s_b2d[h];

    const float4* a4 = (const float4*)(act2d + ((size_t)q*NN + k)*C2d);
    #pragma unroll 4
    for (int c4 = 0; c4 < 32; c4++) {
        float4 a = a4[c4];
        float av[4] = {a.x, a.y, a.z, a.w};
        #pragma unroll
        for (int u = 0; u < 4; u++) {
            int c = c4*4 + u;
            const float* wr = s_w2d + c*12;
            #pragma unroll
            for (int h = 0; h < 12; h++) acc[h] += av[u] * wr[h];
        }
    }

    float maskterm = -1e5f * (1.f - s_mq[qi]*s_mk[ki]);
    #pragma unroll
    for (int h = 0; h < 12; h++) {
        float d = 0.f;
        #pragma unroll
        for (int c = 0; c < 16; c++) d += s_q[qi][h*16+c] * s_k[ki][h*16+c];
        float pd = 0.f;
        #pragma unroll
        for (int i = 0; i < 12; i++) pd += s_qp[qi][h*12+i] * s_kp[ki][h*12+i];
        float d2 = s_sq[qi][h] + s_sk[ki][h] - 2.f*pd;
        float l = acc[h] + d - 0.5f*s_pw[h]*d2 + maskterm;
        g_attn[(size_t)q*(HH*NN) + h*NN + k] = l * 0.57735026919f; // sqrt(1/3)
    }
}

// =====================================================================
// K3: softmax over keys. 9216 rows of 768, 256 threads / block.
// =====================================================================
__global__ void k3_softmax() {
    int r = blockIdx.x;
    float* row = g_attn + (size_t)r*NN;
    int tid = threadIdx.x;
    float v0 = row[tid], v1 = row[tid+256], v2 = row[tid+512];
    float m = fmaxf(fmaxf(v0, v1), v2);
    __shared__ float sred[8];
    #pragma unroll
    for (int o = 16; o; o >>= 1) m = fmaxf(m, __shfl_xor_sync(0xffffffffu, m, o));
    if ((tid & 31) == 0) sred[tid >> 5] = m;
    __syncthreads();
    float mm = sred[0];
    #pragma unroll
    for (int i = 1; i < 8; i++) mm = fmaxf(mm, sred[i]);
    float e0 = expf(v0 - mm), e1 = expf(v1 - mm), e2 = expf(v2 - mm);
    float s = e0 + e1 + e2;
    #pragma unroll
    for (int o = 16; o; o >>= 1) s += __shfl_xor_sync(0xffffffffu, s, o);
    __syncthreads();
    if ((tid & 31) == 0) sred[tid >> 5] = s;
    __syncthreads();
    float ss = 0.f;
    #pragma unroll
    for (int i = 0; i < 8; i++) ss += sred[i];
    float rc = 1.f / ss;
    row[tid] = e0*rc; row[tid+256] = e1*rc; row[tid+512] = e2*rc;
}

// =====================================================================
// K4: r2d = attn @ act_2d. 768 blocks x 128 threads; attn row in smem.
// =====================================================================
__global__ void k4_r2d(const float* __restrict__ act2d) {
    int q = blockIdx.x;
    int tid = threadIdx.x; // 128, owns channel c = tid
    __shared__ float s_attn[NN*HH]; // [j][h], 36 KB
    for (int i = tid; i < NN*HH; i += 128) {
        int h = i / NN, j = i % NN;
        s_attn[j*12 + h] = g_attn[(size_t)q*(HH*NN) + i];
    }
    __syncthreads();
    float acc[12];
    #pragma unroll
    for (int h = 0; h < 12; h++) acc[h] = 0.f;
    const float* base = act2d + (size_t)q*NN*C2d + tid;
    for (int j = 0; j < NN; j++) {
        float a = __ldg(base + (size_t)j*C2d);
        const float* w = s_attn + j*12;
        #pragma unroll
        for (int h = 0; h < 12; h++) acc[h] += a * w[h];
    }
    #pragma unroll
    for (int h = 0; h < 12; h++)
        g_cbuf[q*CONCAT + 576 + h*128 + tid] = acc[h];
}

// =====================================================================
// K5: attn @ [v | vp] per head, tiled. Grid (6 qtiles of 128, 12 heads).
// =====================================================================
__global__ void k5_av() {
    __shared__ float sA[128][33];
    __shared__ float sB[32][40];
    int h = blockIdx.y;
    int q0 = blockIdx.x * 128;
    int tid = threadIdx.x; // 256
    float acc[20];
    #pragma unroll
    for (int t = 0; t < 20; t++) acc[t] = 0.f;

    for (int k0 = 0; k0 < NN; k0 += 32) {
        {
            int row = tid >> 1, cs = (tid & 1) * 16;
            const float* src = g_attn + (size_t)(q0 + row)*(HH*NN) + h*NN + k0 + cs;
            float4 a0 = *(const float4*)(src + 0);
            float4 a1 = *(const float4*)(src + 4);
            float4 a2 = *(const float4*)(src + 8);
            float4 a3 = *(const float4*)(src + 12);
            sA[row][cs+0]=a0.x; sA[row][cs+1]=a0.y; sA[row][cs+2]=a0.z; sA[row][cs+3]=a0.w;
            sA[row][cs+4]=a1.x; sA[row][cs+5]=a1.y; sA[row][cs+6]=a1.z; sA[row][cs+7]=a1.w;
            sA[row][cs+8]=a2.x; sA[row][cs+9]=a2.y; sA[row][cs+10]=a2.z; sA[row][cs+11]=a2.w;
            sA[row][cs+12]=a3.x; sA[row][cs+13]=a3.y; sA[row][cs+14]=a3.z; sA[row][cs+15]=a3.w;
        }
        for (int i = tid; i < 32*40; i += 256) {
            int kk = i / 40, c = i % 40;
            float v = (c < 16)
                ? g_vh [h*(NN*SVd)   + (k0+kk)*SVd   + c]
                : g_vph[h*(NN*PVd*3) + (k0+kk)*PVd*3 + (c-16)];
            sB[kk][c] = v;
        }
        __syncthreads();
        #pragma unroll
        for (int t = 0; t < 20; t++) {
            int o = t*256 + tid;
            int qq = o / 40, c = o % 40;
            float a = 0.f;
            #pragma unroll
            for (int kk = 0; kk < 32; kk++) a += sA[qq][kk] * sB[kk][c];
            acc[t] += a;
        }
        __syncthreads();
    }
    #pragma unroll
    for (int t = 0; t < 20; t++) {
        int o = t*256 + tid;
        int qq = o / 40, c = o % 40;
        int q = q0 + qq;
        if (c < 16) g_cbuf[q*CONCAT + h*16 + c] = acc[t];
        else        g_rpg [q*(HH*PVd*3) + h*(PVd*3) + (c-16)] = acc[t];
    }
}

// =====================================================================
// K5b: invert frames + norms. 768 blocks x 96 threads.
// =====================================================================
__global__ void k5b_fin(const float* __restrict__ rot,
                        const float* __restrict__ trans) {
    int q = blockIdx.x;
    int tid = threadIdx.x; // 96 = h*8+p
    float t0 = g_rpg[q*288 + tid*3+0] - trans[q*3+0];
    float t1 = g_rpg[q*288 + tid*3+1] - trans[q*3+1];
    float t2 = g_rpg[q*288 + tid*3+2] - trans[q*3+2];
    const float* R = rot + q*9;
    float r0 = R[0]*t0 + R[3]*t1 + R[6]*t2;  // R^T * t
    float r1 = R[1]*t0 + R[4]*t1 + R[7]*t2;
    float r2 = R[2]*t0 + R[5]*t1 + R[8]*t2;
    float* cb = g_cbuf + q*CONCAT;
    cb[192 + 0*96 + tid] = r0;
    cb[192 + 1*96 + tid] = r1;
    cb[192 + 2*96 + tid] = r2;
    cb[480 + tid] = sqrtf(r0*r0 + r1*r1 + r2*r2);
}

// =====================================================================
// K6: out = cbuf @ wfin + bfin. M=768, N=384, K=2112. Tiles 64x64x16.
// =====================================================================
__global__ void k6_out(const float* __restrict__ wfin,
                       const float* __restrict__ bfin,
                       float* __restrict__ out) {
    __shared__ float sA[64][17];
    __shared__ float sB[16][68];
    int m0 = blockIdx.x * 64, n0 = blockIdx.y * 64;
    int tid = threadIdx.x; // 256
    int tx = tid & 15, ty = tid >> 4;
    float acc[4][4];
    #pragma unroll
    for (int i = 0; i < 4; i++)
        #pragma unroll
        for (int j = 0; j < 4; j++) acc[i][j] = 0.f;

    for (int k0 = 0; k0 < CONCAT; k0 += 16) {
        {
            int row = tid >> 2, c = (tid & 3) * 4;
            float4 a = *(const float4*)(g_cbuf + (m0+row)*CONCAT + k0 + c);
            sA[row][c] = a.x; sA[row][c+1] = a.y; sA[row][c+2] = a.z; sA[row][c+3] = a.w;
        }
        {
            int r = tid >> 4, c = (tid & 15) * 4;
            float4 b = *(const float4*)(wfin + (k0+r)*384 + n0 + c);
            sB[r][c] = b.x; sB[r][c+1] = b.y; sB[r][c+2] = b.z; sB[r][c+3] = b.w;
        }
        __syncthreads();
        #pragma unroll
        for (int kk = 0; kk < 16; kk++) {
            float a[4], b[4];
            #pragma unroll
            for (int i = 0; i < 4; i++) a[i] = sA[ty*4+i][kk];
            #pragma unroll
            for (int j = 0; j < 4; j++) b[j] = sB[kk][tx*4+j];
            #pragma unroll
            for (int i = 0; i < 4; i++)
                #pragma unroll
                for (int j = 0; j < 4; j++) acc[i][j] += a[i]*b[j];
        }
        __syncthreads();
    }
    #pragma unroll
    for (int i = 0; i < 4; i++)
        #pragma unroll
        for (int j = 0; j < 4; j++)
            out[(m0+ty*4+i)*384 + n0+tx*4+j] = acc[i][j] + bfin[n0+tx*4+j];
}

// =====================================================================
extern "C" void kernel_launch(void* const* d_in, const int* in_sizes, int n_in,
                              void* d_out, int out_size) {
    const float* act   = (const float*)d_in[0];
    const float* act2d = (const float*)d_in[1];
    const float* smask = (const float*)d_in[2];
    const float* rot   = (const float*)d_in[3];
    const float* trans = (const float*)d_in[4];
    const float* wq    = (const float*)d_in[5];
    const float* wk    = (const float*)d_in[6];
    const float* wv    = (const float*)d_in[7];
    const float* wqp   = (const float*)d_in[8];
    const float* bqp   = (const float*)d_in[9];
    const float* wkp   = (const float*)d_in[10];
    const float* bkp   = (const float*)d_in[11];
    const float* wvp   = (const float*)d_in[12];
    const float* bvp   = (const float*)d_in[13];
    const float* w2d   = (const float*)d_in[14];
    const float* b2d   = (const float*)d_in[15];
    const float* wfin  = (const float*)d_in[16];
    const float* bfin  = (const float*)d_in[17];
    const float* tw    = (const float*)d_in[18];
    float* out = (float*)d_out;

    k1_proj<<<NN, 576>>>(act, rot, trans, wq, wk, wv, wqp, bqp, wkp, bkp, wvp, bvp);
    k2_logits<<<dim3(NN/8, NN/16), 128>>>(act2d, w2d, b2d, tw, smask);
    k3_softmax<<<NN*HH, 256>>>();
    k4_r2d<<<NN, 128>>>(act2d);
    k5_av<<<dim3(NN/128, HH), 256>>>();
    k5b_fin<<<NN, 96>>>(rot, trans);
    k6_out<<<dim3(NN/64, 384/64), 256>>>(wfin, bfin, out);
}

// round 5
// speedup vs baseline: 2.2971x; 2.2971x over previous
#include <cuda_runtime.h>
#include <math.h>

#define NN 768
#define HH 12
#define SQKd 16
#define SVd 16
#define PQKd 4
#define PVd 8
#define C1d 384
#define C2d 128
#define CONCAT 2112   // H*(SV + 4*PV + C2) = 12*176
#define NPROJ 1152    // 192*3 + 144*2 + 288

// -------- scratch (device globals; no allocation allowed) --------
__device__ __align__(16) float g_wcat[C1d*NPROJ];
__device__ __align__(16) float g_bcat[NPROJ];
__device__ __align__(16) float g_proj[NN*NPROJ];
__device__ __align__(16) float g_q  [NN*HH*SQKd];        // [n][h*16+c], scaled by 0.25
__device__ __align__(16) float g_k  [NN*HH*SQKd];
__device__ __align__(16) float g_vh [HH*NN*SVd];         // [h][n][c]
__device__ __align__(16) float g_qp [NN*HH*PQKd*3];      // [n][h*12 + p*3 + d] global frame
__device__ __align__(16) float g_kp [NN*HH*PQKd*3];
__device__ __align__(16) float g_vph[HH*NN*PVd*3];       // [h][n][p*3+d] global frame
__device__ __align__(16) float g_sq [NN*HH];
__device__ __align__(16) float g_sk [NN*HH];
__device__ __align__(16) float g_attn[(size_t)NN*HH*NN]; // [q][h][k]
__device__ __align__(16) float g_rpg[NN*HH*PVd*3];
__device__ __align__(16) float g_cbuf[NN*CONCAT];

// -------- f32x2 packed math helpers --------
typedef unsigned long long ull;
__device__ __forceinline__ ull pack2(float x, float y) {
    ull r; asm("mov.b64 %0, {%1, %2};" : "=l"(r) : "f"(x), "f"(y)); return r;
}
__device__ __forceinline__ float2 unpack2(ull v) {
    float2 r; asm("mov.b64 {%0, %1}, %2;" : "=f"(r.x), "=f"(r.y) : "l"(v)); return r;
}
__device__ __forceinline__ ull ffma2(ull a, ull b, ull c) {
    ull d; asm("fma.rn.f32x2 %0, %1, %2, %3;" : "=l"(d) : "l"(a), "l"(b), "l"(c)); return d;
}

// =====================================================================
// KP: pack projection weights into one concat matrix [384 x 1152] + bias
// =====================================================================
__global__ void kpack(const float* __restrict__ wq, const float* __restrict__ wk,
                      const float* __restrict__ wv,
                      const float* __restrict__ wqp, const float* __restrict__ bqp,
                      const float* __restrict__ wkp, const float* __restrict__ bkp,
                      const float* __restrict__ wvp, const float* __restrict__ bvp) {
    int idx = blockIdx.x*256 + threadIdx.x;
    if (idx >= C1d*NPROJ) return;
    int c = idx / NPROJ, col = idx % NPROJ;
    float v;
    if (col < 192)      v = wq [c*192 + col];
    else if (col < 384) v = wk [c*192 + col-192];
    else if (col < 576) v = wv [c*192 + col-384];
    else if (col < 720) v = wqp[c*144 + col-576];
    else if (col < 864) v = wkp[c*144 + col-720];
    else                v = wvp[c*288 + col-864];
    g_wcat[idx] = v;
    if (c == 0) {
        float b = 0.f;
        if (col >= 576 && col < 720) b = bqp[col-576];
        else if (col >= 720 && col < 864) b = bkp[col-720];
        else if (col >= 864) b = bvp[col-864];
        g_bcat[col] = b;
    }
}

// =====================================================================
// Generic tiled GEMM: C[M,N] = A[M,K] @ B[K,N] + bias[N]
// 64x64 tiles, k-chunk 16, 256 threads, f32x2 packed over n pairs.
// Requires M%64==0, N%64==0, K%16==0.
// =====================================================================
__global__ void gemm64(const float* __restrict__ A, const float* __restrict__ B,
                       const float* __restrict__ bias, float* __restrict__ C,
                       int K, int N) {
    __shared__ float sA[64][17];
    __shared__ float sB[16][68];
    int m0 = blockIdx.x * 64, n0 = blockIdx.y * 64;
    int tid = threadIdx.x;
    int tx = tid & 15, ty = tid >> 4;
    ull acc2[4][2];
    ull z = pack2(0.f, 0.f);
    #pragma unroll
    for (int i = 0; i < 4; i++) { acc2[i][0] = z; acc2[i][1] = z; }

    for (int k0 = 0; k0 < K; k0 += 16) {
        {
            int row = tid >> 2, c = (tid & 3) * 4;
            float4 a = *(const float4*)(A + (size_t)(m0+row)*K + k0 + c);
            sA[row][c] = a.x; sA[row][c+1] = a.y; sA[row][c+2] = a.z; sA[row][c+3] = a.w;
        }
        {
            int r = tid >> 4, c = (tid & 15) * 4;
            float4 b = *(const float4*)(B + (size_t)(k0+r)*N + n0 + c);
            sB[r][c] = b.x; sB[r][c+1] = b.y; sB[r][c+2] = b.z; sB[r][c+3] = b.w;
        }
        __syncthreads();
        #pragma unroll
        for (int kk = 0; kk < 16; kk++) {
            ull b20 = *(const ull*)&sB[kk][tx*4];
            ull b21 = *(const ull*)&sB[kk][tx*4+2];
            #pragma unroll
            for (int i = 0; i < 4; i++) {
                float a = sA[ty*4+i][kk];
                ull a2 = pack2(a, a);
                acc2[i][0] = ffma2(a2, b20, acc2[i][0]);
                acc2[i][1] = ffma2(a2, b21, acc2[i][1]);
            }
        }
        __syncthreads();
    }
    #pragma unroll
    for (int i = 0; i < 4; i++) {
        float2 v0 = unpack2(acc2[i][0]);
        float2 v1 = unpack2(acc2[i][1]);
        float* dst = C + (size_t)(m0+ty*4+i)*N + n0 + tx*4;
        dst[0] = v0.x + bias[n0+tx*4+0];
        dst[1] = v0.y + bias[n0+tx*4+1];
        dst[2] = v1.x + bias[n0+tx*4+2];
        dst[3] = v1.y + bias[n0+tx*4+3];
    }
}

// =====================================================================
// K1b: scatter q/k/v, apply rigid frames to points, compute sq/sk.
// 768 blocks x 576 threads. Reads g_proj row.
// =====================================================================
__global__ void k1b(const float* __restrict__ rot, const float* __restrict__ trans) {
    int n = blockIdx.x;
    int tid = threadIdx.x; // 576
    __shared__ float s_p[NPROJ];
    __shared__ float s_app[96*3];
    __shared__ float s_rot[9], s_tr[3];
    for (int i = tid; i < NPROJ; i += 576) s_p[i] = g_proj[(size_t)n*NPROJ + i];
    if (tid < 9) s_rot[tid] = rot[n*9 + tid];
    if (tid < 3) s_tr[tid]  = trans[n*3 + tid];
    __syncthreads();

    if (tid < 192)      g_q[n*192 + tid] = s_p[tid] * 0.25f;
    else if (tid < 384) { int o = tid-192; g_k[n*192 + o] = s_p[192 + o]; }
    else { int o = tid-384; g_vh[(o >> 4)*(NN*SVd) + n*SVd + (o & 15)] = s_p[384 + o]; }

    const float* raw = s_p + 576; // qp 0:144 | kp 144:288 | vp 288:576
    if (tid < 192) {
        float l0, l1, l2;
        if (tid < 48) {
            int h = tid >> 2, p = tid & 3;
            l0 = raw[h*12 + p]; l1 = raw[h*12 + 4 + p]; l2 = raw[h*12 + 8 + p];
        } else if (tid < 96) {
            int j = tid - 48; int h = j >> 2, p = j & 3;
            l0 = raw[144 + h*12 + p]; l1 = raw[144 + h*12 + 4 + p]; l2 = raw[144 + h*12 + 8 + p];
        } else {
            int j = tid - 96; int h = j >> 3, p = j & 7;
            l0 = raw[288 + h*24 + p]; l1 = raw[288 + h*24 + 8 + p]; l2 = raw[288 + h*24 + 16 + p];
        }
        float gx = s_rot[0]*l0 + s_rot[1]*l1 + s_rot[2]*l2 + s_tr[0];
        float gy = s_rot[3]*l0 + s_rot[4]*l1 + s_rot[5]*l2 + s_tr[1];
        float gz = s_rot[6]*l0 + s_rot[7]*l1 + s_rot[8]*l2 + s_tr[2];
        if (tid < 48) {
            g_qp[n*144 + tid*3+0] = gx; g_qp[n*144 + tid*3+1] = gy; g_qp[n*144 + tid*3+2] = gz;
            s_app[tid*3+0] = gx; s_app[tid*3+1] = gy; s_app[tid*3+2] = gz;
        } else if (tid < 96) {
            int j = tid - 48;
            g_kp[n*144 + j*3+0] = gx; g_kp[n*144 + j*3+1] = gy; g_kp[n*144 + j*3+2] = gz;
            s_app[tid*3+0] = gx; s_app[tid*3+1] = gy; s_app[tid*3+2] = gz;
        } else {
            int j = tid - 96; int h = j >> 3, p = j & 7;
            g_vph[h*(NN*PVd*3) + n*(PVd*3) + p*3+0] = gx;
            g_vph[h*(NN*PVd*3) + n*(PVd*3) + p*3+1] = gy;
            g_vph[h*(NN*PVd*3) + n*(PVd*3) + p*3+2] = gz;
        }
    }
    __syncthreads();
    if (tid < 24) {
        int h = tid % 12;
        int base = (tid < 12) ? 0 : 144;
        float s = 0.f;
        #pragma unroll
        for (int p = 0; p < 4; p++) {
            float x = s_app[base + (h*4+p)*3+0];
            float y = s_app[base + (h*4+p)*3+1];
            float z = s_app[base + (h*4+p)*3+2];
            s += x*x + y*y + z*z;
        }
        if (tid < 12) g_sq[n*12 + h] = s; else g_sk[n*12 + h] = s;
    }
}

// =====================================================================
// K2a: Z = act2d @ w2d + b2d -> g_attn[q][h][k]. Coalesced smem-tiled.
// Block: 256 pairs (one q, k0..k0+255), 256 threads, head pairs in f32x2.
// =====================================================================
__global__ void k2a(const float* __restrict__ act2d,
                    const float* __restrict__ w2d,
                    const float* __restrict__ b2d) {
    __shared__ float s_a[256][33];
    __shared__ ull s_w[128][6];
    int tid = threadIdx.x;
    int q = blockIdx.x / 3, k0 = (blockIdx.x % 3) * 256;

    for (int i = tid; i < 128*6; i += 256) {
        int c = i / 6, hh = i % 6;
        s_w[c][hh] = pack2(w2d[c*12 + hh*2], w2d[c*12 + hh*2 + 1]);
    }
    ull acc[6];
    #pragma unroll
    for (int hh = 0; hh < 6; hh++) acc[hh] = pack2(b2d[hh*2], b2d[hh*2+1]);

    const float* base = act2d + ((size_t)q*NN + k0)*C2d;
    for (int c0 = 0; c0 < 128; c0 += 32) {
        for (int i = tid; i < 256*8; i += 256) {
            int r = i >> 3, c4 = i & 7;
            float4 v = *(const float4*)(base + (size_t)r*C2d + c0 + c4*4);
            s_a[r][c4*4+0] = v.x; s_a[r][c4*4+1] = v.y;
            s_a[r][c4*4+2] = v.z; s_a[r][c4*4+3] = v.w;
        }
        __syncthreads();
        #pragma unroll 8
        for (int c = 0; c < 32; c++) {
            float a = s_a[tid][c];
            ull a2 = pack2(a, a);
            #pragma unroll
            for (int hh = 0; hh < 6; hh++) acc[hh] = ffma2(a2, s_w[c0+c][hh], acc[hh]);
        }
        __syncthreads();
    }
    float* dst = g_attn + (size_t)q*(HH*NN) + k0 + tid;
    #pragma unroll
    for (int hh = 0; hh < 6; hh++) {
        float2 v = unpack2(acc[hh]);
        dst[(size_t)(2*hh)*NN] = v.x;
        dst[(size_t)(2*hh+1)*NN] = v.y;
    }
}

// =====================================================================
// K2b: add qk-dot + point-distance + mask terms, scale. Per head.
// Grid (4 ktiles of 192, 12 qtiles of 64, 12 heads), 256 threads.
// pw folded into qp so one accumulator covers qk + pw*qp.kp.
// =====================================================================
__global__ void k2b(const float* __restrict__ smask, const float* __restrict__ tw) {
    int k0 = blockIdx.x * 192, q0 = blockIdx.y * 64, h = blockIdx.z;
    int tid = threadIdx.x;
    __shared__ float s_qc[64][28];
    __shared__ float s_kc[28][192];
    __shared__ float s_sq[64], s_sk[192], s_mq[64], s_mk[192];
    float pw = 0.23570226039f * log1pf(expf(tw[h]));

    for (int i = tid; i < 64*16;  i += 256) { int r=i>>4, c=i&15;  s_qc[r][c]    = g_q [(q0+r)*192 + h*16 + c]; }
    for (int i = tid; i < 64*12;  i += 256) { int r=i/12, c=i%12;  s_qc[r][16+c] = pw * g_qp[(q0+r)*144 + h*12 + c]; }
    for (int i = tid; i < 192*16; i += 256) { int kk=i>>4, c=i&15; s_kc[c][kk]    = g_k [(k0+kk)*192 + h*16 + c]; }
    for (int i = tid; i < 192*12; i += 256) { int kk=i/12, c=i%12; s_kc[16+c][kk] = g_kp[(k0+kk)*144 + h*12 + c]; }
    if (tid < 64)  { s_sq[tid] = g_sq[(q0+tid)*12 + h]; s_mq[tid] = smask[q0+tid]; }
    if (tid < 192) { s_sk[tid] = g_sk[(k0+tid)*12 + h]; s_mk[tid] = smask[k0+tid]; }
    __syncthreads();

    int tc = tid & 31, tr = tid >> 5;   // k = k0 + tc + 32*jj ; q = q0 + tr*8 + i
    ull acc2[8][3];
    ull z = pack2(0.f, 0.f);
    #pragma unroll
    for (int i = 0; i < 8; i++) { acc2[i][0]=z; acc2[i][1]=z; acc2[i][2]=z; }

    #pragma unroll 4
    for (int c = 0; c < 28; c++) {
        const float* kr = &s_kc[c][tc];
        ull b2[3];
        #pragma unroll
        for (int jp = 0; jp < 3; jp++) b2[jp] = pack2(kr[32*(2*jp)], kr[32*(2*jp+1)]);
        #pragma unroll
        for (int i = 0; i < 8; i++) {
            float a = s_qc[tr*8+i][c];
            ull a2 = pack2(a, a);
            acc2[i][0] = ffma2(a2, b2[0], acc2[i][0]);
            acc2[i][1] = ffma2(a2, b2[1], acc2[i][1]);
            acc2[i][2] = ffma2(a2, b2[2], acc2[i][2]);
        }
    }
    #pragma unroll
    for (int i = 0; i < 8; i++) {
        int q = q0 + tr*8 + i;
        float sqv = s_sq[tr*8+i], mq = s_mq[tr*8+i];
        float* row = g_attn + (size_t)q*(HH*NN) + h*NN + k0 + tc;
        #pragma unroll
        for (int jp = 0; jp < 3; jp++) {
            float2 v = unpack2(acc2[i][jp]);
            int j0 = 32*(2*jp), j1 = 32*(2*jp+1);
            float l0 = row[j0] + v.x - 0.5f*pw*(sqv + s_sk[tc+j0]) - 1e5f*(1.f - mq*s_mk[tc+j0]);
            float l1 = row[j1] + v.y - 0.5f*pw*(sqv + s_sk[tc+j1]) - 1e5f*(1.f - mq*s_mk[tc+j1]);
            row[j0] = l0 * 0.57735026919f;
            row[j1] = l1 * 0.57735026919f;
        }
    }
}

// =====================================================================
// K3: softmax over keys. 9216 rows of 768.
// =====================================================================
__global__ void k3_softmax() {
    int r = blockIdx.x;
    float* row = g_attn + (size_t)r*NN;
    int tid = threadIdx.x;
    float v0 = row[tid], v1 = row[tid+256], v2 = row[tid+512];
    float m = fmaxf(fmaxf(v0, v1), v2);
    __shared__ float sred[8];
    #pragma unroll
    for (int o = 16; o; o >>= 1) m = fmaxf(m, __shfl_xor_sync(0xffffffffu, m, o));
    if ((tid & 31) == 0) sred[tid >> 5] = m;
    __syncthreads();
    float mm = sred[0];
    #pragma unroll
    for (int i = 1; i < 8; i++) mm = fmaxf(mm, sred[i]);
    float e0 = expf(v0 - mm), e1 = expf(v1 - mm), e2 = expf(v2 - mm);
    float s = e0 + e1 + e2;
    #pragma unroll
    for (int o = 16; o; o >>= 1) s += __shfl_xor_sync(0xffffffffu, s, o);
    __syncthreads();
    if ((tid & 31) == 0) sred[tid >> 5] = s;
    __syncthreads();
    float ss = 0.f;
    #pragma unroll
    for (int i = 0; i < 8; i++) ss += sred[i];
    float rc = 1.f / ss;
    row[tid] = e0*rc; row[tid+256] = e1*rc; row[tid+512] = e2*rc;
}

// =====================================================================
// K4: r2d = attn @ act_2d. 768 blocks x 512 threads (4-way j split).
// =====================================================================
__global__ void k4_r2d(const float* __restrict__ act2d) {
    int q = blockIdx.x;
    int tid = threadIdx.x; // 512
    __shared__ float s_at[NN*12]; // [j][h] transposed
    for (int i = tid; i < NN*HH; i += 512) {
        int h = i / NN, j = i % NN;
        s_at[j*12 + h] = g_attn[(size_t)q*(HH*NN) + i];
    }
    __syncthreads();
    int c = tid & 127, part = tid >> 7;
    ull acc2[6];
    ull z = pack2(0.f, 0.f);
    #pragma unroll
    for (int hh = 0; hh < 6; hh++) acc2[hh] = z;

    const float* base = act2d + ((size_t)q*NN + part*192)*C2d + c;
    for (int j = 0; j < 192; j++) {
        float a = __ldg(base + (size_t)j*C2d);
        ull a2 = pack2(a, a);
        const ull* w = (const ull*)(s_at + (part*192 + j)*12);
        #pragma unroll
        for (int hh = 0; hh < 6; hh++) acc2[hh] = ffma2(a2, w[hh], acc2[hh]);
    }
    __syncthreads();
    #pragma unroll
    for (int hh = 0; hh < 6; hh++) {
        float2 v = unpack2(acc2[hh]);
        s_at[(part*128 + c)*12 + 2*hh]   = v.x;
        s_at[(part*128 + c)*12 + 2*hh+1] = v.y;
    }
    __syncthreads();
    for (int i = tid; i < 128*12; i += 512) {
        int cc = i / 12, hh = i % 12;
        float s = 0.f;
        #pragma unroll
        for (int p = 0; p < 4; p++) s += s_at[(p*128 + cc)*12 + hh];
        g_cbuf[q*CONCAT + 576 + hh*128 + cc] = s;
    }
}

// =====================================================================
// K5: attn @ [v | vp] per head, register-tiled (2q x 5c per thread).
// Grid (12 qtiles of 64, 12 heads), 256 threads.
// =====================================================================
__global__ void k5_av() {
    __shared__ float sA[64][65];
    __shared__ float sB[64][40];
    int h = blockIdx.y;
    int q0 = blockIdx.x * 64;
    int tid = threadIdx.x;
    int tc = tid & 7, tr = tid >> 3;  // c = tc*5+j, q = q0 + tr*2 + i
    float acc[2][5];
    #pragma unroll
    for (int i = 0; i < 2; i++)
        #pragma unroll
        for (int j = 0; j < 5; j++) acc[i][j] = 0.f;

    for (int k0 = 0; k0 < NN; k0 += 64) {
        for (int i = tid; i < 64*16; i += 256) {
            int r = i >> 4, c4 = i & 15;
            float4 v = *(const float4*)(g_attn + (size_t)(q0+r)*(HH*NN) + h*NN + k0 + c4*4);
            sA[r][c4*4+0] = v.x; sA[r][c4*4+1] = v.y; sA[r][c4*4+2] = v.z; sA[r][c4*4+3] = v.w;
        }
        for (int i = tid; i < 64*40; i += 256) {
            int kk = i / 40, c = i % 40;
            sB[kk][c] = (c < 16)
                ? g_vh [h*(NN*SVd)   + (k0+kk)*SVd   + c]
                : g_vph[h*(NN*PVd*3) + (k0+kk)*PVd*3 + (c-16)];
        }
        __syncthreads();
        #pragma unroll 8
        for (int kk = 0; kk < 64; kk++) {
            float a0 = sA[tr*2][kk], a1 = sA[tr*2+1][kk];
            float b[5];
            #pragma unroll
            for (int j = 0; j < 5; j++) b[j] = sB[kk][tc*5+j];
            #pragma unroll
            for (int j = 0; j < 5; j++) { acc[0][j] += a0*b[j]; acc[1][j] += a1*b[j]; }
        }
        __syncthreads();
    }
    #pragma unroll
    for (int i = 0; i < 2; i++) {
        int q = q0 + tr*2 + i;
        #pragma unroll
        for (int j = 0; j < 5; j++) {
            int c = tc*5 + j;
            if (c < 16) g_cbuf[q*CONCAT + h*16 + c] = acc[i][j];
            else        g_rpg [q*(HH*PVd*3) + h*(PVd*3) + (c-16)] = acc[i][j];
        }
    }
}

// =====================================================================
// K5b: invert frames + norms. 768 blocks x 96 threads.
// =====================================================================
__global__ void k5b_fin(const float* __restrict__ rot,
                        const float* __restrict__ trans) {
    int q = blockIdx.x;
    int tid = threadIdx.x; // 96 = h*8+p
    float t0 = g_rpg[q*288 + tid*3+0] - trans[q*3+0];
    float t1 = g_rpg[q*288 + tid*3+1] - trans[q*3+1];
    float t2 = g_rpg[q*288 + tid*3+2] - trans[q*3+2];
    const float* R = rot + q*9;
    float r0 = R[0]*t0 + R[3]*t1 + R[6]*t2;
    float r1 = R[1]*t0 + R[4]*t1 + R[7]*t2;
    float r2 = R[2]*t0 + R[5]*t1 + R[8]*t2;
    float* cb = g_cbuf + q*CONCAT;
    cb[192 + 0*96 + tid] = r0;
    cb[192 + 1*96 + tid] = r1;
    cb[192 + 2*96 + tid] = r2;
    cb[480 + tid] = sqrtf(r0*r0 + r1*r1 + r2*r2);
}

// =====================================================================
extern "C" void kernel_launch(void* const* d_in, const int* in_sizes, int n_in,
                              void* d_out, int out_size) {
    const float* act   = (const float*)d_in[0];
    const float* act2d = (const float*)d_in[1];
    const float* smask = (const float*)d_in[2];
    const float* rot   = (const float*)d_in[3];
    const float* trans = (const float*)d_in[4];
    const float* wq    = (const float*)d_in[5];
    const float* wk    = (const float*)d_in[6];
    const float* wv    = (const float*)d_in[7];
    const float* wqp   = (const float*)d_in[8];
    const float* bqp   = (const float*)d_in[9];
    const float* wkp   = (const float*)d_in[10];
    const float* bkp   = (const float*)d_in[11];
    const float* wvp   = (const float*)d_in[12];
    const float* bvp   = (const float*)d_in[13];
    const float* w2d   = (const float*)d_in[14];
    const float* b2d   = (const float*)d_in[15];
    const float* wfin  = (const float*)d_in[16];
    const float* bfin  = (const float*)d_in[17];
    const float* tw    = (const float*)d_in[18];
    float* out = (float*)d_out;

    float *p_wcat, *p_bcat, *p_proj, *p_cbuf;
    cudaGetSymbolAddress((void**)&p_wcat, g_wcat);
    cudaGetSymbolAddress((void**)&p_bcat, g_bcat);
    cudaGetSymbolAddress((void**)&p_proj, g_proj);
    cudaGetSymbolAddress((void**)&p_cbuf, g_cbuf);

    kpack<<<(C1d*NPROJ + 255)/256, 256>>>(wq, wk, wv, wqp, bqp, wkp, bkp, wvp, bvp);
    gemm64<<<dim3(NN/64, NPROJ/64), 256>>>(act, p_wcat, p_bcat, p_proj, C1d, NPROJ);
    k1b<<<NN, 576>>>(rot, trans);
    k2a<<<NN*3, 256>>>(act2d, w2d, b2d);
    k2b<<<dim3(4, 12, 12), 256>>>(smask, tw);
    k3_softmax<<<NN*HH, 256>>>();
    k4_r2d<<<NN, 512>>>(act2d);
    k5_av<<<dim3(12, 12), 256>>>();
    k5b_fin<<<NN, 96>>>(rot, trans);
    gemm64<<<dim3(NN/64, 384/64), 256>>>(p_cbuf, wfin, bfin, out, CONCAT, 384);
}